// round 13
// baseline (speedup 1.0000x reference)
#include <cuda_runtime.h>
#include <cuda_bf16.h>
#include <cstdint>

#define N_SEGMENTS 50000
#define N_FEAT4    16          // float4 per row (64 floats)
#define CAP        44          // bucket cap; lambda=19.2 rows/seg at x=0.60, P(>44)~1e-7/seg
#define OVF_MAX    (1 << 20)

#define GRID_BLKS  1184        // 148 SM x 8 blocks @256thr
#define GB_BLOCKS  832         // gather-role blocks (finish ~71us, then steal RED work)
#define RED_CHUNK  128         // rows per steal (16 groups x 8 rows)
#define ZERO_BLKS  320         // prologue blocks that zero d_out; rest scatter

// ---------------------------------------------------------------------------
// Static device scratch (no allocations allowed).
// g_cnt tail carries the counters so ONE memset node resets everything:
//   g_cnt[N_SEGMENTS + 0] = overflow count
//   g_cnt[N_SEGMENTS + 1] = steal work counter
// ---------------------------------------------------------------------------
__device__ int g_cnt[N_SEGMENTS + 8];
__device__ int g_bucket[N_SEGMENTS * CAP];   // 8.8 MB, L2-resident
__device__ int g_ovf[OVF_MAX];

#define OVF_N   (g_cnt[N_SEGMENTS + 0])
#define WORK_N  (g_cnt[N_SEGMENTS + 1])

__device__ __forceinline__ bool idx_is64(const void* idx_raw) {
    const unsigned int* w = (const unsigned int*)idx_raw;
    unsigned int acc = w[1] | w[3] | w[5] | w[7] | w[9] | w[11] | w[13] | w[15];
    return acc == 0u;
}

__device__ __forceinline__ float4 add4(float4 a, float4 b) {
    return make_float4(a.x + b.x, a.y + b.y, a.z + b.z, a.w + b.w);
}

__device__ __forceinline__ void red_v4(float* dst, float4 v) {
    asm volatile("red.global.add.v4.f32 [%0], {%1, %2, %3, %4};"
                 :: "l"(dst), "f"(v.x), "f"(v.y), "f"(v.z), "f"(v.w) : "memory");
}

// ---------------------------------------------------------------------------
// Kernel 1 (prologue): zero d_out AND scatter row ids [0,H) into buckets.
// No ordering dependency between the two jobs -> overlapped block roles.
// ---------------------------------------------------------------------------
__global__ void __launch_bounds__(256)
prologue_kernel(float4* __restrict__ out, const void* __restrict__ idx_raw,
                int H, int n_vec4) {
    if (blockIdx.x < ZERO_BLKS) {
        const float4 z = make_float4(0.f, 0.f, 0.f, 0.f);
        const int t = blockIdx.x * 256 + threadIdx.x;
        for (int i = t; i < n_vec4; i += ZERO_BLKS * 256) out[i] = z;
        return;
    }

    const bool is64 = idx_is64(idx_raw);
    const int t = (blockIdx.x - ZERO_BLKS) * 256 + threadIdx.x;
    const int nthreads = (GRID_BLKS - ZERO_BLKS) * 256;

    for (int base = t * 4; base < H; base += nthreads * 4) {
        int s[4];
        const int cnt = min(4, H - base);
        if (cnt == 4) {
            if (!is64) {
                int4 a = __ldcs((const int4*)((const int*)idx_raw + base));
                s[0] = a.x; s[1] = a.y; s[2] = a.z; s[3] = a.w;
            } else {
                const int4* ip = (const int4*)((const long long*)idx_raw + base);
                int4 a = __ldcs(ip), b = __ldcs(ip + 1);
                s[0] = a.x; s[1] = a.z; s[2] = b.x; s[3] = b.z;
            }
        } else {
            for (int k = 0; k < cnt; ++k)
                s[k] = is64 ? (int)((const long long*)idx_raw)[base + k]
                            : ((const int*)idx_raw)[base + k];
        }
        #pragma unroll
        for (int k = 0; k < 4; ++k) {
            if (k < cnt) {
                int slot = atomicAdd(&g_cnt[s[k]], 1);
                if (slot < CAP) {
                    g_bucket[s[k] * CAP + slot] = base + k;
                } else {
                    int o = atomicAdd(&OVF_N, 1);
                    if (o < OVF_MAX) g_ovf[o] = base + k;
                }
            }
        }
    }
}

// ---------------------------------------------------------------------------
// Kernel 2 (phase B):
//  Blocks [0, GB_BLOCKS): warp-per-segment gather over bucketed rows [0,H),
//    register accumulation, RED epilogue; overflow fixup; then join steal.
//  Blocks [GB_BLOCKS, GRID_BLKS): steal 128-row chunks of [H, n_rows) and
//    RED-scatter them.
// ---------------------------------------------------------------------------
__global__ void __launch_bounds__(256)
fused_kernel(const float4* __restrict__ in,
             const void* __restrict__ idx_raw,
             float* __restrict__ out,
             int H, int n_rows) {
    const bool is64 = idx_is64(idx_raw);

    if (blockIdx.x < GB_BLOCKS) {
        // ================= gather role =================
        __shared__ int sm_bk[8][CAP];
        const int wblk = threadIdx.x >> 5;
        const int lane = threadIdx.x & 31;
        const int half = lane >> 4;
        const int col  = lane & 15;
        const int nwarps = GB_BLOCKS * 8;

        for (int g = blockIdx.x * 8 + wblk; g < N_SEGMENTS; g += nwarps) {
            int n = g_cnt[g];
            if (n > CAP) n = CAP;
            if (n == 0) continue;                      // uniform per warp

            sm_bk[wblk][lane] = g_bucket[g * CAP + lane];
            if (lane < CAP - 32)
                sm_bk[wblk][32 + lane] = g_bucket[g * CAP + 32 + lane];
            __syncwarp();
            const int* sbk = sm_bk[wblk];

            float4 acc0 = make_float4(0.f, 0.f, 0.f, 0.f);
            float4 acc1 = acc0;

            int i = 0;
            for (; i + 8 <= n; i += 8) {
                int r0 = sbk[i + 0 + half];
                int r1 = sbk[i + 2 + half];
                int r2 = sbk[i + 4 + half];
                int r3 = sbk[i + 6 + half];
                float4 v0 = __ldcs(&in[r0 * N_FEAT4 + col]);
                float4 v1 = __ldcs(&in[r1 * N_FEAT4 + col]);
                float4 v2 = __ldcs(&in[r2 * N_FEAT4 + col]);
                float4 v3 = __ldcs(&in[r3 * N_FEAT4 + col]);
                acc0 = add4(acc0, add4(v0, v1));
                acc1 = add4(acc1, add4(v2, v3));
            }
            for (; i + 2 <= n; i += 2) {
                acc0 = add4(acc0, __ldcs(&in[sbk[i + half] * N_FEAT4 + col]));
            }
            if (i < n && half == 0) {
                acc0 = add4(acc0, __ldcs(&in[sbk[i] * N_FEAT4 + col]));
            }

            float4 acc = add4(acc0, acc1);
            acc.x += __shfl_xor_sync(0xffffffffu, acc.x, 16);
            acc.y += __shfl_xor_sync(0xffffffffu, acc.y, 16);
            acc.z += __shfl_xor_sync(0xffffffffu, acc.z, 16);
            acc.w += __shfl_xor_sync(0xffffffffu, acc.w, 16);

            if (half == 0) red_v4(out + g * 64 + col * 4, acc);
            __syncwarp();           // protect sm_bk before next iteration
        }

        // ------- overflow fixup (normally ~0 entries) -------
        int cnt = OVF_N;
        if (cnt > 0) {
            if (cnt > OVF_MAX) cnt = OVF_MAX;
            int t      = blockIdx.x * 256 + threadIdx.x;
            int lane16 = t & 15;
            int e      = t >> 4;
            const int estr = (GB_BLOCKS * 256) >> 4;
            for (; e < cnt; e += estr) {
                int r   = g_ovf[e];
                int seg = is64 ? (int)((const long long*)idx_raw)[r]
                               : ((const int*)idx_raw)[r];
                float4 v = in[r * N_FEAT4 + lane16];
                red_v4(out + seg * 64 + lane16 * 4, v);
            }
        }
        // fall through to the steal loop
    }

    // ================= RED steal loop over [H, n_rows) =================
    {
        __shared__ int sm_chunk;
        const int span = n_rows - H;
        const int grp  = threadIdx.x >> 4;   // 0..15
        const int lane = threadIdx.x & 15;
        const int l4   = lane * 4;

        for (;;) {
            if (threadIdx.x == 0) sm_chunk = atomicAdd(&WORK_N, RED_CHUNK);
            __syncthreads();
            const int chunk = sm_chunk;
            __syncthreads();
            if (chunk >= span) break;

            // Each group handles 2 quads of 4 consecutive rows per chunk.
            #pragma unroll
            for (int q = 0; q < 2; ++q) {
                const int base = H + chunk + (grp + q * 16) * 4;
                if (base >= n_rows) break;

                const int navail = n_rows - base;
                if (navail >= 4) {
                    int s0, s1, s2, s3;
                    if (!is64) {
                        int4 a = __ldg((const int4*)((const int*)idx_raw + base));
                        s0 = a.x; s1 = a.y; s2 = a.z; s3 = a.w;
                    } else {
                        const int4* ip = (const int4*)((const long long*)idx_raw + base);
                        int4 a = __ldg(ip), b = __ldg(ip + 1);
                        s0 = a.x; s1 = a.z; s2 = b.x; s3 = b.z;
                    }
                    const float4* p = in + base * N_FEAT4 + lane;
                    float4 v0 = __ldcs(p);
                    float4 v1 = __ldcs(p + 1 * N_FEAT4);
                    float4 v2 = __ldcs(p + 2 * N_FEAT4);
                    float4 v3 = __ldcs(p + 3 * N_FEAT4);
                    red_v4(out + s0 * 64 + l4, v0);
                    red_v4(out + s1 * 64 + l4, v1);
                    red_v4(out + s2 * 64 + l4, v2);
                    red_v4(out + s3 * 64 + l4, v3);
                } else {
                    for (int k = 0; k < navail; ++k) {
                        int r = base + k;
                        int seg = is64 ? (int)((const long long*)idx_raw)[r]
                                       : ((const int*)idx_raw)[r];
                        float4 v = __ldcs(&in[r * N_FEAT4 + lane]);
                        red_v4(out + seg * 64 + l4, v);
                    }
                }
            }
        }
    }
}

// ---------------------------------------------------------------------------
// Launch: 3 graph nodes total (memset, prologue, phase B).
// ---------------------------------------------------------------------------
extern "C" void kernel_launch(void* const* d_in, const int* in_sizes, int n_in,
                              void* d_out, int out_size) {
    const float4* in  = (const float4*)d_in[0];
    const void*   idx = (const void*)d_in[1];

    const int n_rows = in_sizes[0] / 64;                       // 1,600,000
    const int H = (int)(((long long)n_rows * 60) / 100) & ~7;  // 60% to gather
    const int n_vec4 = out_size / 4;                           // 800K float4

    void* cnt_addr = nullptr;
    cudaGetSymbolAddress(&cnt_addr, g_cnt);
    cudaMemsetAsync(cnt_addr, 0, (size_t)(N_SEGMENTS + 8) * sizeof(int));

    prologue_kernel<<<GRID_BLKS, 256>>>((float4*)d_out, idx, H, n_vec4);

    fused_kernel<<<GRID_BLKS, 256>>>(in, idx, (float*)d_out, H, n_rows);
}

// round 16
// speedup vs baseline: 1.2212x; 1.2212x over previous
#include <cuda_runtime.h>
#include <cuda_bf16.h>
#include <cstdint>

#define N_SEGMENTS 50000
#define N_FEAT4    16          // float4 per row (64 floats)
#define CAP        44          // bucket cap; lambda=19.2 rows/seg at x=0.60, P(>44)~1e-7/seg
#define OVF_MAX    (1 << 20)

#define GRID_BLKS  1184        // 148 SM x 8 blocks @256thr
#define GB_BLOCKS  832         // gather-role blocks (finish early, then steal RED work)
#define RED_CHUNK  64          // rows per steal (16 groups x 4 rows) -- keep regs at 32
#define ZERO_BLKS  320         // prologue blocks that zero d_out; rest scatter

// ---------------------------------------------------------------------------
// Static device scratch (no allocations allowed).
// g_cnt tail carries the counters so ONE memset node resets everything:
//   g_cnt[N_SEGMENTS + 0] = overflow count
//   g_cnt[N_SEGMENTS + 1] = steal work counter
// ---------------------------------------------------------------------------
__device__ int g_cnt[N_SEGMENTS + 8];
__device__ int g_bucket[N_SEGMENTS * CAP];   // 8.8 MB, L2-resident
__device__ int g_ovf[OVF_MAX];

#define OVF_N   (g_cnt[N_SEGMENTS + 0])
#define WORK_N  (g_cnt[N_SEGMENTS + 1])

__device__ __forceinline__ bool idx_is64(const void* idx_raw) {
    const unsigned int* w = (const unsigned int*)idx_raw;
    unsigned int acc = w[1] | w[3] | w[5] | w[7] | w[9] | w[11] | w[13] | w[15];
    return acc == 0u;
}

__device__ __forceinline__ float4 add4(float4 a, float4 b) {
    return make_float4(a.x + b.x, a.y + b.y, a.z + b.z, a.w + b.w);
}

__device__ __forceinline__ void red_v4(float* dst, float4 v) {
    asm volatile("red.global.add.v4.f32 [%0], {%1, %2, %3, %4};"
                 :: "l"(dst), "f"(v.x), "f"(v.y), "f"(v.z), "f"(v.w) : "memory");
}

// ---------------------------------------------------------------------------
// Kernel 1 (prologue): zero d_out AND scatter row ids [0,H) into buckets.
// No ordering dependency between the two jobs -> overlapped block roles.
// ---------------------------------------------------------------------------
__global__ void __launch_bounds__(256)
prologue_kernel(float4* __restrict__ out, const void* __restrict__ idx_raw,
                int H, int n_vec4) {
    if (blockIdx.x < ZERO_BLKS) {
        const float4 z = make_float4(0.f, 0.f, 0.f, 0.f);
        const int t = blockIdx.x * 256 + threadIdx.x;
        for (int i = t; i < n_vec4; i += ZERO_BLKS * 256) out[i] = z;
        return;
    }

    const bool is64 = idx_is64(idx_raw);
    const int t = (blockIdx.x - ZERO_BLKS) * 256 + threadIdx.x;
    const int nthreads = (GRID_BLKS - ZERO_BLKS) * 256;

    for (int base = t * 4; base < H; base += nthreads * 4) {
        int s[4];
        const int cnt = min(4, H - base);
        if (cnt == 4) {
            if (!is64) {
                int4 a = __ldcs((const int4*)((const int*)idx_raw + base));
                s[0] = a.x; s[1] = a.y; s[2] = a.z; s[3] = a.w;
            } else {
                const int4* ip = (const int4*)((const long long*)idx_raw + base);
                int4 a = __ldcs(ip), b = __ldcs(ip + 1);
                s[0] = a.x; s[1] = a.z; s[2] = b.x; s[3] = b.z;
            }
        } else {
            for (int k = 0; k < cnt; ++k)
                s[k] = is64 ? (int)((const long long*)idx_raw)[base + k]
                            : ((const int*)idx_raw)[base + k];
        }
        #pragma unroll
        for (int k = 0; k < 4; ++k) {
            if (k < cnt) {
                int slot = atomicAdd(&g_cnt[s[k]], 1);
                if (slot < CAP) {
                    g_bucket[s[k] * CAP + slot] = base + k;
                } else {
                    int o = atomicAdd(&OVF_N, 1);
                    if (o < OVF_MAX) g_ovf[o] = base + k;
                }
            }
        }
    }
}

// ---------------------------------------------------------------------------
// Kernel 2 (phase B) -- structure identical to the measured-82.1us R12 kernel:
//  Blocks [0, GB_BLOCKS): warp-per-segment gather over bucketed rows [0,H),
//    register accumulation, RED epilogue; overflow fixup; then join steal.
//  Blocks [GB_BLOCKS, GRID_BLKS): steal 64-row chunks of [H, n_rows) and
//    RED-scatter them.
// ---------------------------------------------------------------------------
__global__ void __launch_bounds__(256)
fused_kernel(const float4* __restrict__ in,
             const void* __restrict__ idx_raw,
             float* __restrict__ out,
             int H, int n_rows) {
    const bool is64 = idx_is64(idx_raw);

    if (blockIdx.x < GB_BLOCKS) {
        // ================= gather role =================
        __shared__ int sm_bk[8][CAP];
        const int wblk = threadIdx.x >> 5;
        const int lane = threadIdx.x & 31;
        const int half = lane >> 4;
        const int col  = lane & 15;
        const int nwarps = GB_BLOCKS * 8;

        for (int g = blockIdx.x * 8 + wblk; g < N_SEGMENTS; g += nwarps) {
            int n = g_cnt[g];
            if (n > CAP) n = CAP;
            if (n == 0) continue;                      // uniform per warp

            sm_bk[wblk][lane] = g_bucket[g * CAP + lane];
            if (lane < CAP - 32)
                sm_bk[wblk][32 + lane] = g_bucket[g * CAP + 32 + lane];
            __syncwarp();
            const int* sbk = sm_bk[wblk];

            float4 acc0 = make_float4(0.f, 0.f, 0.f, 0.f);
            float4 acc1 = acc0;

            int i = 0;
            for (; i + 8 <= n; i += 8) {
                int r0 = sbk[i + 0 + half];
                int r1 = sbk[i + 2 + half];
                int r2 = sbk[i + 4 + half];
                int r3 = sbk[i + 6 + half];
                float4 v0 = __ldcs(&in[r0 * N_FEAT4 + col]);
                float4 v1 = __ldcs(&in[r1 * N_FEAT4 + col]);
                float4 v2 = __ldcs(&in[r2 * N_FEAT4 + col]);
                float4 v3 = __ldcs(&in[r3 * N_FEAT4 + col]);
                acc0 = add4(acc0, add4(v0, v1));
                acc1 = add4(acc1, add4(v2, v3));
            }
            for (; i + 2 <= n; i += 2) {
                acc0 = add4(acc0, __ldcs(&in[sbk[i + half] * N_FEAT4 + col]));
            }
            if (i < n && half == 0) {
                acc0 = add4(acc0, __ldcs(&in[sbk[i] * N_FEAT4 + col]));
            }

            float4 acc = add4(acc0, acc1);
            acc.x += __shfl_xor_sync(0xffffffffu, acc.x, 16);
            acc.y += __shfl_xor_sync(0xffffffffu, acc.y, 16);
            acc.z += __shfl_xor_sync(0xffffffffu, acc.z, 16);
            acc.w += __shfl_xor_sync(0xffffffffu, acc.w, 16);

            if (half == 0) red_v4(out + g * 64 + col * 4, acc);
            __syncwarp();           // protect sm_bk before next iteration
        }

        // ------- overflow fixup (normally ~0 entries) -------
        int cnt = OVF_N;
        if (cnt > 0) {
            if (cnt > OVF_MAX) cnt = OVF_MAX;
            int t      = blockIdx.x * 256 + threadIdx.x;
            int lane16 = t & 15;
            int e      = t >> 4;
            const int estr = (GB_BLOCKS * 256) >> 4;
            for (; e < cnt; e += estr) {
                int r   = g_ovf[e];
                int seg = is64 ? (int)((const long long*)idx_raw)[r]
                               : ((const int*)idx_raw)[r];
                float4 v = in[r * N_FEAT4 + lane16];
                red_v4(out + seg * 64 + lane16 * 4, v);
            }
        }
        // fall through to the steal loop
    }

    // ================= RED steal loop over [H, n_rows) =================
    {
        __shared__ int sm_chunk;
        const int span = n_rows - H;
        const int grp  = threadIdx.x >> 4;   // 0..15
        const int lane = threadIdx.x & 15;
        const int l4   = lane * 4;

        for (;;) {
            if (threadIdx.x == 0) sm_chunk = atomicAdd(&WORK_N, RED_CHUNK);
            __syncthreads();
            const int chunk = sm_chunk;
            __syncthreads();
            if (chunk >= span) break;

            const int base = H + chunk + grp * 4;    // 4 consecutive rows
            if (base < n_rows) {
                int s0, s1, s2, s3;
                const int navail = n_rows - base;
                if (navail >= 4) {
                    if (!is64) {
                        int4 a = __ldg((const int4*)((const int*)idx_raw + base));
                        s0 = a.x; s1 = a.y; s2 = a.z; s3 = a.w;
                    } else {
                        const int4* ip = (const int4*)((const long long*)idx_raw + base);
                        int4 a = __ldg(ip), b = __ldg(ip + 1);
                        s0 = a.x; s1 = a.z; s2 = b.x; s3 = b.z;
                    }
                    const float4* p = in + base * N_FEAT4 + lane;
                    float4 v0 = __ldcs(p);
                    float4 v1 = __ldcs(p + 1 * N_FEAT4);
                    float4 v2 = __ldcs(p + 2 * N_FEAT4);
                    float4 v3 = __ldcs(p + 3 * N_FEAT4);
                    red_v4(out + s0 * 64 + l4, v0);
                    red_v4(out + s1 * 64 + l4, v1);
                    red_v4(out + s2 * 64 + l4, v2);
                    red_v4(out + s3 * 64 + l4, v3);
                } else {
                    for (int k = 0; k < navail; ++k) {
                        int r = base + k;
                        int seg = is64 ? (int)((const long long*)idx_raw)[r]
                                       : ((const int*)idx_raw)[r];
                        float4 v = __ldcs(&in[r * N_FEAT4 + lane]);
                        red_v4(out + seg * 64 + l4, v);
                    }
                }
            }
        }
    }
}

// ---------------------------------------------------------------------------
// Launch: 3 graph nodes total (memset, prologue, phase B).
// ---------------------------------------------------------------------------
extern "C" void kernel_launch(void* const* d_in, const int* in_sizes, int n_in,
                              void* d_out, int out_size) {
    const float4* in  = (const float4*)d_in[0];
    const void*   idx = (const void*)d_in[1];

    const int n_rows = in_sizes[0] / 64;                       // 1,600,000
    const int H = (int)(((long long)n_rows * 60) / 100) & ~7;  // 60% to gather
    const int n_vec4 = out_size / 4;                           // 800K float4

    void* cnt_addr = nullptr;
    cudaGetSymbolAddress(&cnt_addr, g_cnt);
    cudaMemsetAsync(cnt_addr, 0, (size_t)(N_SEGMENTS + 8) * sizeof(int));

    prologue_kernel<<<GRID_BLKS, 256>>>((float4*)d_out, idx, H, n_vec4);

    fused_kernel<<<GRID_BLKS, 256>>>(in, idx, (float*)d_out, H, n_rows);
}

// round 17
// speedup vs baseline: 1.2513x; 1.0247x over previous
#include <cuda_runtime.h>
#include <cuda_bf16.h>
#include <cstdint>

#define N_SEGMENTS 50000
#define N_FEAT4    16          // float4 per row (64 floats)
#define CAP        48          // bucket cap; lambda=21.8 rows/seg at x=0.68
#define OVF_MAX    (1 << 20)

#define GRID_BLKS  1184        // 148 SM x 8 blocks @256thr
#define GB_BLOCKS  896         // gather-role blocks
#define RED_CHUNK  64          // rows per steal (16 groups x 4 rows) -- keeps regs at 32
#define ZERO_BLKS  320         // prologue blocks that zero d_out first, then join scatter
#define SC_CHUNK   1024        // scatter steal chunk (256 thr x 4 rows)

// ---------------------------------------------------------------------------
// Static device scratch (no allocations allowed).
// g_cnt tail carries the counters so ONE memset node resets everything:
//   g_cnt[N_SEGMENTS + 0] = overflow count
//   g_cnt[N_SEGMENTS + 1] = RED steal work counter
//   g_cnt[N_SEGMENTS + 2] = scatter steal work counter
// ---------------------------------------------------------------------------
__device__ int g_cnt[N_SEGMENTS + 8];
__device__ int g_bucket[N_SEGMENTS * CAP];   // 9.6 MB, L2-resident
__device__ int g_ovf[OVF_MAX];

#define OVF_N   (g_cnt[N_SEGMENTS + 0])
#define WORK_N  (g_cnt[N_SEGMENTS + 1])
#define SCAT_N  (g_cnt[N_SEGMENTS + 2])

__device__ __forceinline__ bool idx_is64(const void* idx_raw) {
    const unsigned int* w = (const unsigned int*)idx_raw;
    unsigned int acc = w[1] | w[3] | w[5] | w[7] | w[9] | w[11] | w[13] | w[15];
    return acc == 0u;
}

__device__ __forceinline__ float4 add4(float4 a, float4 b) {
    return make_float4(a.x + b.x, a.y + b.y, a.z + b.z, a.w + b.w);
}

__device__ __forceinline__ void red_v4(float* dst, float4 v) {
    asm volatile("red.global.add.v4.f32 [%0], {%1, %2, %3, %4};"
                 :: "l"(dst), "f"(v.x), "f"(v.y), "f"(v.z), "f"(v.w) : "memory");
}

// ---------------------------------------------------------------------------
// Kernel 1 (prologue): zero d_out AND scatter row ids [0,H) into buckets.
// Scatter uses an atomic chunk counter so zero-blocks join scatter after
// finishing (no idle blocks). No ordering hazard: the jobs write disjoint
// destinations, and scatter chunks are independent.
// ---------------------------------------------------------------------------
__global__ void __launch_bounds__(256)
prologue_kernel(float4* __restrict__ out, const void* __restrict__ idx_raw,
                int H, int n_vec4) {
    if (blockIdx.x < ZERO_BLKS) {
        const float4 z = make_float4(0.f, 0.f, 0.f, 0.f);
        const int t = blockIdx.x * 256 + threadIdx.x;
        for (int i = t; i < n_vec4; i += ZERO_BLKS * 256) out[i] = z;
        // fall through to scatter stealing
    }

    const bool is64 = idx_is64(idx_raw);
    __shared__ int sm_c;

    for (;;) {
        if (threadIdx.x == 0) sm_c = atomicAdd(&SCAT_N, SC_CHUNK);
        __syncthreads();
        const int chunk = sm_c;
        __syncthreads();
        if (chunk >= H) break;

        const int base = chunk + threadIdx.x * 4;
        if (base >= H) continue;

        int s[4];
        const int cnt = min(4, H - base);
        if (cnt == 4) {
            if (!is64) {
                int4 a = __ldcs((const int4*)((const int*)idx_raw + base));
                s[0] = a.x; s[1] = a.y; s[2] = a.z; s[3] = a.w;
            } else {
                const int4* ip = (const int4*)((const long long*)idx_raw + base);
                int4 a = __ldcs(ip), b = __ldcs(ip + 1);
                s[0] = a.x; s[1] = a.z; s[2] = b.x; s[3] = b.z;
            }
        } else {
            for (int k = 0; k < cnt; ++k)
                s[k] = is64 ? (int)((const long long*)idx_raw)[base + k]
                            : ((const int*)idx_raw)[base + k];
        }
        #pragma unroll
        for (int k = 0; k < 4; ++k) {
            if (k < cnt) {
                int slot = atomicAdd(&g_cnt[s[k]], 1);
                if (slot < CAP) {
                    g_bucket[s[k] * CAP + slot] = base + k;
                } else {
                    int o = atomicAdd(&OVF_N, 1);
                    if (o < OVF_MAX) g_ovf[o] = base + k;
                }
            }
        }
    }
}

// ---------------------------------------------------------------------------
// Kernel 2 (phase B) -- structure identical to the measured R16 kernel:
//  Blocks [0, GB_BLOCKS): warp-per-segment gather over bucketed rows [0,H),
//    register accumulation, RED epilogue; overflow fixup; then join steal.
//  Blocks [GB_BLOCKS, GRID_BLKS): steal 64-row chunks of [H, n_rows) and
//    RED-scatter them.
// ---------------------------------------------------------------------------
__global__ void __launch_bounds__(256)
fused_kernel(const float4* __restrict__ in,
             const void* __restrict__ idx_raw,
             float* __restrict__ out,
             int H, int n_rows) {
    const bool is64 = idx_is64(idx_raw);

    if (blockIdx.x < GB_BLOCKS) {
        // ================= gather role =================
        __shared__ int sm_bk[8][CAP];
        const int wblk = threadIdx.x >> 5;
        const int lane = threadIdx.x & 31;
        const int half = lane >> 4;
        const int col  = lane & 15;
        const int nwarps = GB_BLOCKS * 8;

        for (int g = blockIdx.x * 8 + wblk; g < N_SEGMENTS; g += nwarps) {
            int n = g_cnt[g];
            if (n > CAP) n = CAP;
            if (n == 0) continue;                      // uniform per warp

            sm_bk[wblk][lane] = g_bucket[g * CAP + lane];
            if (lane < CAP - 32)
                sm_bk[wblk][32 + lane] = g_bucket[g * CAP + 32 + lane];
            __syncwarp();
            const int* sbk = sm_bk[wblk];

            float4 acc0 = make_float4(0.f, 0.f, 0.f, 0.f);
            float4 acc1 = acc0;

            int i = 0;
            for (; i + 8 <= n; i += 8) {
                int r0 = sbk[i + 0 + half];
                int r1 = sbk[i + 2 + half];
                int r2 = sbk[i + 4 + half];
                int r3 = sbk[i + 6 + half];
                float4 v0 = __ldcs(&in[r0 * N_FEAT4 + col]);
                float4 v1 = __ldcs(&in[r1 * N_FEAT4 + col]);
                float4 v2 = __ldcs(&in[r2 * N_FEAT4 + col]);
                float4 v3 = __ldcs(&in[r3 * N_FEAT4 + col]);
                acc0 = add4(acc0, add4(v0, v1));
                acc1 = add4(acc1, add4(v2, v3));
            }
            for (; i + 2 <= n; i += 2) {
                acc0 = add4(acc0, __ldcs(&in[sbk[i + half] * N_FEAT4 + col]));
            }
            if (i < n && half == 0) {
                acc0 = add4(acc0, __ldcs(&in[sbk[i] * N_FEAT4 + col]));
            }

            float4 acc = add4(acc0, acc1);
            acc.x += __shfl_xor_sync(0xffffffffu, acc.x, 16);
            acc.y += __shfl_xor_sync(0xffffffffu, acc.y, 16);
            acc.z += __shfl_xor_sync(0xffffffffu, acc.z, 16);
            acc.w += __shfl_xor_sync(0xffffffffu, acc.w, 16);

            if (half == 0) red_v4(out + g * 64 + col * 4, acc);
            __syncwarp();           // protect sm_bk before next iteration
        }

        // ------- overflow fixup (normally ~0 entries) -------
        int cnt = OVF_N;
        if (cnt > 0) {
            if (cnt > OVF_MAX) cnt = OVF_MAX;
            int t      = blockIdx.x * 256 + threadIdx.x;
            int lane16 = t & 15;
            int e      = t >> 4;
            const int estr = (GB_BLOCKS * 256) >> 4;
            for (; e < cnt; e += estr) {
                int r   = g_ovf[e];
                int seg = is64 ? (int)((const long long*)idx_raw)[r]
                               : ((const int*)idx_raw)[r];
                float4 v = in[r * N_FEAT4 + lane16];
                red_v4(out + seg * 64 + lane16 * 4, v);
            }
        }
        // fall through to the steal loop
    }

    // ================= RED steal loop over [H, n_rows) =================
    {
        __shared__ int sm_chunk;
        const int span = n_rows - H;
        const int grp  = threadIdx.x >> 4;   // 0..15
        const int lane = threadIdx.x & 15;
        const int l4   = lane * 4;

        for (;;) {
            if (threadIdx.x == 0) sm_chunk = atomicAdd(&WORK_N, RED_CHUNK);
            __syncthreads();
            const int chunk = sm_chunk;
            __syncthreads();
            if (chunk >= span) break;

            const int base = H + chunk + grp * 4;    // 4 consecutive rows
            if (base < n_rows) {
                int s0, s1, s2, s3;
                const int navail = n_rows - base;
                if (navail >= 4) {
                    if (!is64) {
                        int4 a = __ldg((const int4*)((const int*)idx_raw + base));
                        s0 = a.x; s1 = a.y; s2 = a.z; s3 = a.w;
                    } else {
                        const int4* ip = (const int4*)((const long long*)idx_raw + base);
                        int4 a = __ldg(ip), b = __ldg(ip + 1);
                        s0 = a.x; s1 = a.z; s2 = b.x; s3 = b.z;
                    }
                    const float4* p = in + base * N_FEAT4 + lane;
                    float4 v0 = __ldcs(p);
                    float4 v1 = __ldcs(p + 1 * N_FEAT4);
                    float4 v2 = __ldcs(p + 2 * N_FEAT4);
                    float4 v3 = __ldcs(p + 3 * N_FEAT4);
                    red_v4(out + s0 * 64 + l4, v0);
                    red_v4(out + s1 * 64 + l4, v1);
                    red_v4(out + s2 * 64 + l4, v2);
                    red_v4(out + s3 * 64 + l4, v3);
                } else {
                    for (int k = 0; k < navail; ++k) {
                        int r = base + k;
                        int seg = is64 ? (int)((const long long*)idx_raw)[r]
                                       : ((const int*)idx_raw)[r];
                        float4 v = __ldcs(&in[r * N_FEAT4 + lane]);
                        red_v4(out + seg * 64 + l4, v);
                    }
                }
            }
        }
    }
}

// ---------------------------------------------------------------------------
// Launch: 3 graph nodes total (memset, prologue, phase B).
// ---------------------------------------------------------------------------
extern "C" void kernel_launch(void* const* d_in, const int* in_sizes, int n_in,
                              void* d_out, int out_size) {
    const float4* in  = (const float4*)d_in[0];
    const void*   idx = (const void*)d_in[1];

    const int n_rows = in_sizes[0] / 64;                       // 1,600,000
    const int H = (int)(((long long)n_rows * 68) / 100) & ~7;  // 68% to gather
    const int n_vec4 = out_size / 4;                           // 800K float4

    void* cnt_addr = nullptr;
    cudaGetSymbolAddress(&cnt_addr, g_cnt);
    cudaMemsetAsync(cnt_addr, 0, (size_t)(N_SEGMENTS + 8) * sizeof(int));

    prologue_kernel<<<GRID_BLKS, 256>>>((float4*)d_out, idx, H, n_vec4);

    fused_kernel<<<GRID_BLKS, 256>>>(in, idx, (float*)d_out, H, n_rows);
}